// round 16
// baseline (speedup 1.0000x reference)
#include <cuda_runtime.h>
#include <cuda_bf16.h>
#include <cstdint>

// ---------------- device scratch (no allocations allowed) ----------------
#define NMAX 4096
__device__ float g_scores[NMAX];
__device__ float g_pm[NMAX * 3];   // xyz / RADIUS
__device__ float g_pc[NMAX * 3];   // xyz / (sqrt(2)*RADIUS)
__device__ float g_uv[NMAX * 6];   // tangent u,v
__device__ float g_mq[NMAX * 8];   // packed mesh inputs: pm.xyz, score, nrm.xyz, 0
__device__ float g_h1[NMAX * 16];  // pre-groupnorm h
__device__ float g_h[NMAX * 16];   // groupnormed h
__device__ float g_nuv[NMAX * 9];  // [n, t1, t2]
__device__ float g_y2[NMAX * 16];  // conv output after no_w MLP
__device__ float g_part1[16 * 8];  // gn_in partials
__device__ float g_part2[16 * 8];  // gn_out partials

__device__ __forceinline__ float lk(float x) { return x >= 0.f ? x : 0.2f * x; }

// relu on the ALU pipe: bits(relu(x)) == max((int)bits(x), 0)
__device__ __forceinline__ float reluf(float x) {
    int v = __float_as_int(x);
    v = v > 0 ? v : 0;
    return __int_as_float(v);
}
// pack two bf16 (lo-first) into .b32
__device__ __forceinline__ uint32_t pkbf(__nv_bfloat16 lo, __nv_bfloat16 hi) {
    __nv_bfloat162 v(lo, hi);
    return *reinterpret_cast<uint32_t*>(&v);
}
// bf16 hi/lo split of fp32: x ~= hi + lo  (residual ~2^-17 x)
__device__ __forceinline__ void bfsplit(float x, __nv_bfloat16& hi, __nv_bfloat16& lo) {
    hi = __float2bfloat16(x);
    lo = __float2bfloat16(x - __bfloat162float(hi));
}
// m16n8k16 bf16 mma, C += A*B (fp32 accum)
__device__ __forceinline__ void mma16(float& c0, float& c1, float& c2, float& c3,
                                      uint32_t a0, uint32_t a1, uint32_t a2, uint32_t a3,
                                      uint32_t b0, uint32_t b1) {
    asm volatile(
        "mma.sync.aligned.m16n8k16.row.col.f32.bf16.bf16.f32 "
        "{%0,%1,%2,%3}, {%4,%5,%6,%7}, {%8,%9}, {%0,%1,%2,%3};"
        : "+f"(c0), "+f"(c1), "+f"(c2), "+f"(c3)
        : "r"(a0), "r"(a1), "r"(a2), "r"(a3), "r"(b0), "r"(b1));
}

// ---------------- Kernel A: per-point preprocessing ----------------
__global__ void kA(const float* __restrict__ xyz, const float* __restrict__ nrm,
                   const float* __restrict__ feats,
                   const float* __restrict__ osw1, const float* __restrict__ osb1,
                   const float* __restrict__ osw2, const float* __restrict__ osb2,
                   const float* __restrict__ niw1, const float* __restrict__ nib1,
                   const float* __restrict__ niw2, const float* __restrict__ nib2,
                   int N) {
    __shared__ float sOs1[256], sNi1[256], sNi2[256];
    __shared__ float sOsb1[16], sOsw2[16], sNib1[16], sNib2[16];
    int t = threadIdx.x;
    if (t < 256) { sOs1[t] = osw1[t]; sNi1[t] = niw1[t]; sNi2[t] = niw2[t]; }
    if (t < 16)  { sOsb1[t] = osb1[t]; sOsw2[t] = osw2[t]; sNib1[t] = nib1[t]; sNib2[t] = nib2[t]; }
    __syncthreads();
    int i = blockIdx.x * 256 + t;
    if (i >= N) return;

    float f[16];
#pragma unroll
    for (int k = 0; k < 16; k++) f[k] = feats[i * 16 + k];

    float sc = osb2[0];
#pragma unroll
    for (int u = 0; u < 16; u++) {
        float a = sOsb1[u];
#pragma unroll
        for (int k = 0; k < 16; k++) a = fmaf(f[k], sOs1[u * 16 + k], a);
        sc = fmaf(lk(a), sOsw2[u], sc);
    }
    g_scores[i] = sc;

    float px = xyz[i * 3 + 0], py = xyz[i * 3 + 1], pz = xyz[i * 3 + 2];
    const float invR = 1.f / 9.f;
    const float invRc = 1.f / (9.f * 1.4142135623730951f);
    float pmx = px * invR, pmy = py * invR, pmz = pz * invR;
    g_pm[i * 3 + 0] = pmx;  g_pm[i * 3 + 1] = pmy;  g_pm[i * 3 + 2] = pmz;
    g_pc[i * 3 + 0] = px * invRc; g_pc[i * 3 + 1] = py * invRc; g_pc[i * 3 + 2] = pz * invRc;

    float nx = nrm[i * 3 + 0], ny = nrm[i * 3 + 1], nz = nrm[i * 3 + 2];
    // packed mesh quad: [pm.xyz, score][nrm.xyz, 0]
    *reinterpret_cast<float4*>(g_mq + i * 8)     = make_float4(pmx, pmy, pmz, sc);
    *reinterpret_cast<float4*>(g_mq + i * 8 + 4) = make_float4(nx, ny, nz, 0.f);

    float s = nz >= 0.f ? 1.f : -1.f;
    float a = -1.f / (s + nz);
    float b = nx * ny * a;
    g_uv[i * 6 + 0] = 1.f + s * nx * nx * a;
    g_uv[i * 6 + 1] = s * b;
    g_uv[i * 6 + 2] = -s * nx;
    g_uv[i * 6 + 3] = b;
    g_uv[i * 6 + 4] = s + ny * ny * a;
    g_uv[i * 6 + 5] = -ny;

    float h0[16];
#pragma unroll
    for (int u = 0; u < 16; u++) {
        float acc = sNib1[u];
#pragma unroll
        for (int k = 0; k < 16; k++) acc = fmaf(f[k], sNi1[u * 16 + k], acc);
        h0[u] = lk(acc);
    }
#pragma unroll
    for (int v = 0; v < 16; v++) {
        float acc = sNib2[v];
#pragma unroll
        for (int k = 0; k < 16; k++) acc = fmaf(h0[k], sNi2[v * 16 + k], acc);
        g_h1[i * 16 + v] = lk(acc);
    }
}

// ---------------- GroupNorm stats: 16 CTAs x 256 thr, one row each ----------------
__device__ void gns_body(const float* __restrict__ xin, float* __restrict__ part) {
    __shared__ float red[8][8];
    int t = threadIdx.x;
    int n = blockIdx.x * 256 + t;
    const float4* rp = reinterpret_cast<const float4*>(xin + n * 16);
    float4 v0 = rp[0], v1 = rp[1], v2 = rp[2], v3 = rp[3];
    float s0 = v0.x + v0.y + v0.z + v0.w, q0 = v0.x * v0.x + v0.y * v0.y + v0.z * v0.z + v0.w * v0.w;
    float s1 = v1.x + v1.y + v1.z + v1.w, q1 = v1.x * v1.x + v1.y * v1.y + v1.z * v1.z + v1.w * v1.w;
    float s2 = v2.x + v2.y + v2.z + v2.w, q2 = v2.x * v2.x + v2.y * v2.y + v2.z * v2.z + v2.w * v2.w;
    float s3 = v3.x + v3.y + v3.z + v3.w, q3 = v3.x * v3.x + v3.y * v3.y + v3.z * v3.z + v3.w * v3.w;
#pragma unroll
    for (int off = 16; off > 0; off >>= 1) {
        s0 += __shfl_down_sync(0xffffffffu, s0, off);
        s1 += __shfl_down_sync(0xffffffffu, s1, off);
        s2 += __shfl_down_sync(0xffffffffu, s2, off);
        s3 += __shfl_down_sync(0xffffffffu, s3, off);
        q0 += __shfl_down_sync(0xffffffffu, q0, off);
        q1 += __shfl_down_sync(0xffffffffu, q1, off);
        q2 += __shfl_down_sync(0xffffffffu, q2, off);
        q3 += __shfl_down_sync(0xffffffffu, q3, off);
    }
    int lane = t & 31, w = t >> 5;
    if (lane == 0) {
        red[w][0] = s0; red[w][1] = s1; red[w][2] = s2; red[w][3] = s3;
        red[w][4] = q0; red[w][5] = q1; red[w][6] = q2; red[w][7] = q3;
    }
    __syncthreads();
    if (t < 8) {
        float a = 0.f;
#pragma unroll
        for (int k = 0; k < 8; k++) a += red[k][t];
        part[blockIdx.x * 8 + t] = a;
    }
}
__global__ void kGNs1(int N) { gns_body(g_h1, g_part1); }
__global__ void kGNs2(int N) { gns_body(g_y2, g_part2); }

// stats finalize helper (in-block): fin[8] -> smean[4], sinv[4]
__device__ __forceinline__ void gn_finalize(const float* __restrict__ part,
                                            float* fin, float* smean, float* sinv, int N) {
    int t = threadIdx.x;
    if (t < 8) {
        float a = 0.f;
#pragma unroll
        for (int c = 0; c < 16; c++) a += part[c * 8 + t];
        fin[t] = a;
    }
    __syncthreads();
    if (t < 4) {
        float cnt = (float)(4 * N);
        float mn = fin[t] / cnt;
        float vv = fin[t + 4] / cnt - mn * mn;
        smean[t] = mn;
        sinv[t] = rsqrtf(vv + 1e-5f);
    }
    __syncthreads();
}

// ---------------- GroupNorm apply (gn_in): 256 CTAs ----------------
__global__ void kGNa_in(const float* __restrict__ gamma, const float* __restrict__ beta, int N) {
    __shared__ float fin[8], smean[4], sinv[4];
    gn_finalize(g_part1, fin, smean, sinv, N);
    int idx = blockIdx.x * 256 + threadIdx.x;
    int c = idx & 15;
    int gg = c >> 2;
    g_h[idx] = (g_h1[idx] - smean[gg]) * sinv[gg] * gamma[c] + beta[c];
}

// ---------------- GroupNorm apply (gn_out) fused with kE3 ----------------
__global__ void kGNaE3(const float* __restrict__ gamma, const float* __restrict__ beta,
                       const float* __restrict__ feats,
                       const float* __restrict__ llw1, const float* __restrict__ llb1,
                       const float* __restrict__ llw2, const float* __restrict__ llb2,
                       const float* __restrict__ ltw, const float* __restrict__ ltb,
                       float* __restrict__ out, int N) {
    __shared__ float fin[8], smean[4], sinv[4];
    __shared__ float yn_s[16][17], t1_s[16][17];
    __shared__ float sW1[256], sW2[256], sWt[256], sB1[16], sB2[16], sBt[16];
    int t = threadIdx.x;
    if (t < 256) { sW1[t] = llw1[t]; sW2[t] = llw2[t]; sWt[t] = ltw[t]; }
    if (t < 16)  { sB1[t] = llb1[t]; sB2[t] = llb2[t]; sBt[t] = ltb[t]; }
    gn_finalize(g_part2, fin, smean, sinv, N);

    int il = t >> 4, c = t & 15;
    int i = blockIdx.x * 16 + il;
    int gg = c >> 2;
    float x = g_y2[i * 16 + c];
    yn_s[il][c] = (x - smean[gg]) * sinv[gg] * gamma[c] + beta[c];
    __syncthreads();
    float a = sB1[c];
#pragma unroll
    for (int k = 0; k < 16; k++) a = fmaf(yn_s[il][k], sW1[c * 16 + k], a);
    t1_s[il][c] = fmaxf(a, 0.f);
    __syncthreads();
    float xi = sB2[c];
#pragma unroll
    for (int k = 0; k < 16; k++) xi = fmaf(t1_s[il][k], sW2[c * 16 + k], xi);
    float xl = sBt[c];
#pragma unroll
    for (int k = 0; k < 16; k++) xl = fmaf(feats[i * 16 + k], sWt[c * 16 + k], xl);
    out[i * 16 + c] = xl + xi;
}

// ---------------- Kernel C: load_mesh N^2 (packed float4 loads + 2-way ILP) ----------------
// CTA = 4 i's x 64 j-lanes. Thread (il = t>>6, s = t&63) sums j = s+128k and s+64+128k.
// Consecutive lanes read consecutive j; g_mq gives 2 coalesced LDG.128 per j.
__global__ void kMesh(const float* __restrict__ nrm, int N) {
    __shared__ float sred[4][64][2];
    int t = threadIdx.x;
    int il = t >> 6, s = t & 63;
    int i = blockIdx.x * 4 + il;

    float pix = g_pm[i * 3 + 0], piy = g_pm[i * 3 + 1], piz = g_pm[i * 3 + 2];
    float nix = nrm[i * 3 + 0], niy = nrm[i * 3 + 1], niz = nrm[i * 3 + 2];
    float ux = g_uv[i * 6 + 0], uy = g_uv[i * 6 + 1], uz = g_uv[i * 6 + 2];
    float vx = g_uv[i * 6 + 3], vy = g_uv[i * 6 + 4], vz = g_uv[i * 6 + 5];

    float ov0a = 0.f, ov1a = 0.f, ov0b = 0.f, ov1b = 0.f;
#pragma unroll 2
    for (int j = s; j < N; j += 128) {
        int jb = j + 64;
        float4 pa = *reinterpret_cast<const float4*>(g_mq + j * 8);
        float4 na = *reinterpret_cast<const float4*>(g_mq + j * 8 + 4);
        float4 pb = *reinterpret_cast<const float4*>(g_mq + jb * 8);
        float4 nb = *reinterpret_cast<const float4*>(g_mq + jb * 8 + 4);

        float dxa = pa.x - pix, dya = pa.y - piy, dza = pa.z - piz;
        float d2a = dxa * dxa + dya * dya + dza * dza;
        float csa = na.x * nix + na.y * niy + na.z * niz;
        float tta = 2.f - csa;
        float wja = __expf(-d2a * tta * tta) * pa.w;
        ov0a = fmaf(wja, ux * dxa + uy * dya + uz * dza, ov0a);
        ov1a = fmaf(wja, vx * dxa + vy * dya + vz * dza, ov1a);

        float dxb = pb.x - pix, dyb = pb.y - piy, dzb = pb.z - piz;
        float d2b = dxb * dxb + dyb * dyb + dzb * dzb;
        float csb = nb.x * nix + nb.y * niy + nb.z * niz;
        float ttb = 2.f - csb;
        float wjb = __expf(-d2b * ttb * ttb) * pb.w;
        ov0b = fmaf(wjb, ux * dxb + uy * dyb + uz * dzb, ov0b);
        ov1b = fmaf(wjb, vx * dxb + vy * dyb + vz * dzb, ov1b);
    }
    sred[il][s][0] = ov0a + ov0b;
    sred[il][s][1] = ov1a + ov1b;
    __syncthreads();
    if (t < 4) {
        float a0 = 0.f, a1 = 0.f;
#pragma unroll 8
        for (int k = 0; k < 64; k++) { a0 += sred[t][k][0]; a1 += sred[t][k][1]; }
        a0 += 1e-5f; a1 += 1e-5f;
        float nr = fmaxf(sqrtf(a0 * a0 + a1 * a1), 1e-12f);
        int ii = blockIdx.x * 4 + t;
        float ex = a0 / nr, ey = a1 / nr;
        float mx = nrm[ii * 3 + 0], my = nrm[ii * 3 + 1], mz = nrm[ii * 3 + 2];
        float uxx = g_uv[ii * 6 + 0], uyy = g_uv[ii * 6 + 1], uzz = g_uv[ii * 6 + 2];
        float vxx = g_uv[ii * 6 + 3], vyy = g_uv[ii * 6 + 4], vzz = g_uv[ii * 6 + 5];
        g_nuv[ii * 9 + 0] = mx; g_nuv[ii * 9 + 1] = my; g_nuv[ii * 9 + 2] = mz;
        g_nuv[ii * 9 + 3] = ex * uxx + ey * vxx;
        g_nuv[ii * 9 + 4] = ex * uyy + ey * vyy;
        g_nuv[ii * 9 + 5] = ex * uzz + ey * vzz;
        g_nuv[ii * 9 + 6] = -ey * uxx + ex * vxx;
        g_nuv[ii * 9 + 7] = -ey * uyy + ex * vyy;
        g_nuv[ii * 9 + 8] = -ey * uzz + ex * vzz;
    }
}

// ---------------- Kernel D: bf16 mma conv (R7 exact) + fused no_w MLP tail ----------------
__global__ void __launch_bounds__(256, 3)
kConvB(const float* __restrict__ nrm, const float* __restrict__ cva1,
       const float* __restrict__ cvb1, const float* __restrict__ cva2,
       const float* __restrict__ cvb2,
       const float* __restrict__ now1, const float* __restrict__ nob1,
       const float* __restrict__ now2, const float* __restrict__ nob2, int N) {
    __shared__ __align__(16) uint32_t sGp[128][12]; // words 0-3: hi pairs, 4-7: lo pairs
    __shared__ float sWh[128 * 17];
    __shared__ float sRed[8][4][4];
    __shared__ float s_a1[24], s_b1[8], s_pi[3], s_nv[9];
    __shared__ float yv[16], t1e[16];

    int t = threadIdx.x, lane = t & 31, w = t >> 5;
    int r = lane >> 2, q = lane & 3;
    int i = blockIdx.x;

    if (t < 24) s_a1[t] = cva1[t];
    else if (t < 32) s_b1[t - 24] = cvb1[t - 24];
    else if (t < 35) s_pi[t - 32] = g_pc[i * 3 + (t - 32)];
    else if (t < 44) s_nv[t - 35] = g_nuv[i * 9 + (t - 35)];

    uint32_t Bhi[4], Blo[4];
    float bias0[4], bias1[4];
#pragma unroll
    for (int lc = 0; lc < 4; lc++) {
        int h = 2 * w + (lc >> 1);
        int oB = (lc & 1) * 8 + r;
        const float* brow = cva2 + (oB * 16 + h) * 8;
        float v0 = brow[2 * q], v1 = brow[2 * q + 1];
        __nv_bfloat16 h0, l0, h1, l1;
        bfsplit(v0, h0, l0);
        bfsplit(v1, h1, l1);
        Bhi[lc] = pkbf(h0, h1);
        Blo[lc] = pkbf(l0, l1);
        int oC = (lc & 1) * 8 + 2 * q;
        bias0[lc] = cvb2[oC * 16 + h];
        bias1[lc] = cvb2[(oC + 1) * 16 + h];
    }
    __syncthreads();

    float y4[4] = {0.f, 0.f, 0.f, 0.f};

    for (int jt = 0; jt < N; jt += 128) {
        __syncthreads();
        {
            int jj = t & 127;
            int j = jt + jj;
            float pjx = g_pc[j * 3 + 0], pjy = g_pc[j * 3 + 1], pjz = g_pc[j * 3 + 2];
            float dx = pjx - s_pi[0], dy = pjy - s_pi[1], dz = pjz - s_pi[2];
            if (t < 128) {
                float X0 = dx * s_nv[0] + dy * s_nv[1] + dz * s_nv[2];
                float X1 = dx * s_nv[3] + dy * s_nv[4] + dz * s_nv[5];
                float X2 = dx * s_nv[6] + dy * s_nv[7] + dz * s_nv[8];
                uint32_t hp[4], lp[4];
#pragma unroll
                for (int c2 = 0; c2 < 4; c2++) {
                    float g0 = fmaf(X0, s_a1[(2 * c2) * 3 + 0],
                               fmaf(X1, s_a1[(2 * c2) * 3 + 1],
                               fmaf(X2, s_a1[(2 * c2) * 3 + 2], s_b1[2 * c2])));
                    float g1 = fmaf(X0, s_a1[(2 * c2 + 1) * 3 + 0],
                               fmaf(X1, s_a1[(2 * c2 + 1) * 3 + 1],
                               fmaf(X2, s_a1[(2 * c2 + 1) * 3 + 2], s_b1[2 * c2 + 1])));
                    g0 = fmaxf(g0, 0.f);
                    g1 = fmaxf(g1, 0.f);
                    __nv_bfloat16 h0, l0, h1, l1;
                    bfsplit(g0, h0, l0);
                    bfsplit(g1, h1, l1);
                    hp[c2] = pkbf(h0, h1);
                    lp[c2] = pkbf(l0, l1);
                }
                *reinterpret_cast<uint4*>(&sGp[jj][0]) = make_uint4(hp[0], hp[1], hp[2], hp[3]);
                *reinterpret_cast<uint4*>(&sGp[jj][4]) = make_uint4(lp[0], lp[1], lp[2], lp[3]);
            } else {
                float njx = nrm[j * 3 + 0], njy = nrm[j * 3 + 1], njz = nrm[j * 3 + 2];
                float d2 = dx * dx + dy * dy + dz * dz;
                float cs = njx * s_nv[0] + njy * s_nv[1] + njz * s_nv[2];
                float tt = 2.f - cs;
                float wv = __expf(-d2 * tt * tt);
                const float4* hp4 = reinterpret_cast<const float4*>(g_h + j * 16);
                float* whd = sWh + jj * 17;
#pragma unroll
                for (int c = 0; c < 4; c++) {
                    float4 h4 = hp4[c];
                    whd[4 * c + 0] = wv * h4.x;
                    whd[4 * c + 1] = wv * h4.y;
                    whd[4 * c + 2] = wv * h4.z;
                    whd[4 * c + 3] = wv * h4.w;
                }
            }
        }
        __syncthreads();

#pragma unroll 2
        for (int mt = 0; mt < 8; mt++) {
            int row0 = mt * 16 + r, row1 = row0 + 8;
            uint32_t a0 = sGp[row0][q];
            uint32_t a1 = sGp[row1][q];
            uint32_t a2 = sGp[row0][4 + q];
            uint32_t a3 = sGp[row1][4 + q];
            float whA0 = sWh[row0 * 17 + 2 * w];
            float whA1 = sWh[row1 * 17 + 2 * w];
            float whB0 = sWh[row0 * 17 + 2 * w + 1];
            float whB1 = sWh[row1 * 17 + 2 * w + 1];
#pragma unroll
            for (int lc = 0; lc < 4; lc++) {
                float c0 = bias0[lc], c1 = bias1[lc], c2 = bias0[lc], c3 = bias1[lc];
                mma16(c0, c1, c2, c3, a0, a1, a2, a3, Bhi[lc], Bhi[lc]);
                mma16(c0, c1, c2, c3, a0, a1, a2, a3, Blo[lc], Blo[lc]);
                float w0 = (lc >> 1) ? whB0 : whA0;
                float w1 = (lc >> 1) ? whB1 : whA1;
                int base = (lc & 1) * 2;
                y4[base + 0] = fmaf(reluf(c0), w0, fmaf(reluf(c2), w1, y4[base + 0]));
                y4[base + 1] = fmaf(reluf(c1), w0, fmaf(reluf(c3), w1, y4[base + 1]));
            }
        }
    }

#pragma unroll
    for (int off = 4; off < 32; off <<= 1) {
        y4[0] += __shfl_down_sync(0xffffffffu, y4[0], off);
        y4[1] += __shfl_down_sync(0xffffffffu, y4[1], off);
        y4[2] += __shfl_down_sync(0xffffffffu, y4[2], off);
        y4[3] += __shfl_down_sync(0xffffffffu, y4[3], off);
    }
    if (lane < 4) {
        sRed[w][lane][0] = y4[0];
        sRed[w][lane][1] = y4[1];
        sRed[w][lane][2] = y4[2];
        sRed[w][lane][3] = y4[3];
    }
    __syncthreads();
    if (t < 16) {
        int o = t;
        int qq = (o & 7) >> 1;
        int slot = (o & 1) + ((o >> 3) << 1);
        float a = 0.f;
#pragma unroll
        for (int ww = 0; ww < 8; ww++) a += sRed[ww][qq][slot];
        yv[o] = a;
    }
    __syncthreads();
    if (t < 16) {
        float a = nob1[t];
#pragma unroll
        for (int k = 0; k < 16; k++) a = fmaf(yv[k], now1[t * 16 + k], a);
        t1e[t] = lk(a);
    }
    __syncthreads();
    if (t < 16) {
        float a = nob2[t];
#pragma unroll
        for (int k = 0; k < 16; k++) a = fmaf(t1e[k], now2[t * 16 + k], a);
        g_y2[i * 16 + t] = lk(a);
    }
}

// ---------------- launch ----------------
extern "C" void kernel_launch(void* const* d_in, const int* in_sizes, int n_in,
                              void* d_out, int out_size) {
    const float* xyz    = (const float*)d_in[0];
    const float* nrm    = (const float*)d_in[1];
    const float* feats  = (const float*)d_in[2];
    const float* osw1   = (const float*)d_in[3];
    const float* osb1   = (const float*)d_in[4];
    const float* osw2   = (const float*)d_in[5];
    const float* osb2   = (const float*)d_in[6];
    const float* niw1   = (const float*)d_in[7];
    const float* nib1   = (const float*)d_in[8];
    const float* niw2   = (const float*)d_in[9];
    const float* nib2   = (const float*)d_in[10];
    const float* gnig   = (const float*)d_in[11];
    const float* gnib   = (const float*)d_in[12];
    const float* cva1   = (const float*)d_in[13];
    const float* cvb1   = (const float*)d_in[14];
    const float* cva2   = (const float*)d_in[15];
    const float* cvb2   = (const float*)d_in[16];
    const float* now1   = (const float*)d_in[17];
    const float* nob1   = (const float*)d_in[18];
    const float* now2   = (const float*)d_in[19];
    const float* nob2   = (const float*)d_in[20];
    const float* gnog   = (const float*)d_in[21];
    const float* gnob   = (const float*)d_in[22];
    const float* llw1   = (const float*)d_in[23];
    const float* llb1   = (const float*)d_in[24];
    const float* llw2   = (const float*)d_in[25];
    const float* llb2   = (const float*)d_in[26];
    const float* ltw    = (const float*)d_in[27];
    const float* ltb    = (const float*)d_in[28];
    float* out = (float*)d_out;

    int N = in_sizes[0] / 3;  // 4096

    kA<<<(N + 255) / 256, 256>>>(xyz, nrm, feats, osw1, osb1, osw2, osb2,
                                 niw1, nib1, niw2, nib2, N);
    kGNs1<<<N / 256, 256>>>(N);
    kGNa_in<<<N * 16 / 256, 256>>>(gnig, gnib, N);
    kMesh<<<N / 4, 256>>>(nrm, N);
    kConvB<<<N, 256>>>(nrm, cva1, cvb1, cva2, cvb2, now1, nob1, now2, nob2, N);
    kGNs2<<<N / 256, 256>>>(N);
    kGNaE3<<<N / 16, 256>>>(gnog, gnob, feats, llw1, llb1, llw2, llb2, ltw, ltb, out, N);
}

// round 17
// speedup vs baseline: 1.0174x; 1.0174x over previous
#include <cuda_runtime.h>
#include <cuda_bf16.h>
#include <cstdint>

// ---------------- device scratch (no allocations allowed) ----------------
#define NMAX 4096
__device__ float g_scores[NMAX];
__device__ float g_pm[NMAX * 3];   // xyz / RADIUS
__device__ float g_pc[NMAX * 3];   // xyz / (sqrt(2)*RADIUS)
__device__ float g_uv[NMAX * 6];   // tangent u,v
__device__ float g_h1[NMAX * 16];  // pre-groupnorm h
__device__ float g_h[NMAX * 16];   // groupnormed h
__device__ float g_nuv[NMAX * 9];  // [n, t1, t2]
__device__ float g_y2[NMAX * 16];  // conv output after no_w MLP
__device__ float g_part1[16 * 8];  // gn_in partials
__device__ float g_part2[16 * 8];  // gn_out partials

__device__ __forceinline__ float lk(float x) { return x >= 0.f ? x : 0.2f * x; }

// relu on the ALU pipe: bits(relu(x)) == max((int)bits(x), 0)
__device__ __forceinline__ float reluf(float x) {
    int v = __float_as_int(x);
    v = v > 0 ? v : 0;
    return __int_as_float(v);
}
// pack two bf16 (lo-first) into .b32
__device__ __forceinline__ uint32_t pkbf(__nv_bfloat16 lo, __nv_bfloat16 hi) {
    __nv_bfloat162 v(lo, hi);
    return *reinterpret_cast<uint32_t*>(&v);
}
// bf16 hi/lo split of fp32: x ~= hi + lo  (residual ~2^-17 x)
__device__ __forceinline__ void bfsplit(float x, __nv_bfloat16& hi, __nv_bfloat16& lo) {
    hi = __float2bfloat16(x);
    lo = __float2bfloat16(x - __bfloat162float(hi));
}
// m16n8k16 bf16 mma, C += A*B (fp32 accum)
__device__ __forceinline__ void mma16(float& c0, float& c1, float& c2, float& c3,
                                      uint32_t a0, uint32_t a1, uint32_t a2, uint32_t a3,
                                      uint32_t b0, uint32_t b1) {
    asm volatile(
        "mma.sync.aligned.m16n8k16.row.col.f32.bf16.bf16.f32 "
        "{%0,%1,%2,%3}, {%4,%5,%6,%7}, {%8,%9}, {%0,%1,%2,%3};"
        : "+f"(c0), "+f"(c1), "+f"(c2), "+f"(c3)
        : "r"(a0), "r"(a1), "r"(a2), "r"(a3), "r"(b0), "r"(b1));
}

// ---------------- Kernel A: per-point preprocessing ----------------
__global__ void kA(const float* __restrict__ xyz, const float* __restrict__ nrm,
                   const float* __restrict__ feats,
                   const float* __restrict__ osw1, const float* __restrict__ osb1,
                   const float* __restrict__ osw2, const float* __restrict__ osb2,
                   const float* __restrict__ niw1, const float* __restrict__ nib1,
                   const float* __restrict__ niw2, const float* __restrict__ nib2,
                   int N) {
    __shared__ float sOs1[256], sNi1[256], sNi2[256];
    __shared__ float sOsb1[16], sOsw2[16], sNib1[16], sNib2[16];
    int t = threadIdx.x;
    if (t < 256) { sOs1[t] = osw1[t]; sNi1[t] = niw1[t]; sNi2[t] = niw2[t]; }
    if (t < 16)  { sOsb1[t] = osb1[t]; sOsw2[t] = osw2[t]; sNib1[t] = nib1[t]; sNib2[t] = nib2[t]; }
    __syncthreads();
    int i = blockIdx.x * 256 + t;
    if (i >= N) return;

    float f[16];
#pragma unroll
    for (int k = 0; k < 16; k++) f[k] = feats[i * 16 + k];

    float sc = osb2[0];
#pragma unroll
    for (int u = 0; u < 16; u++) {
        float a = sOsb1[u];
#pragma unroll
        for (int k = 0; k < 16; k++) a = fmaf(f[k], sOs1[u * 16 + k], a);
        sc = fmaf(lk(a), sOsw2[u], sc);
    }
    g_scores[i] = sc;

    float px = xyz[i * 3 + 0], py = xyz[i * 3 + 1], pz = xyz[i * 3 + 2];
    const float invR = 1.f / 9.f;
    const float invRc = 1.f / (9.f * 1.4142135623730951f);
    g_pm[i * 3 + 0] = px * invR;  g_pm[i * 3 + 1] = py * invR;  g_pm[i * 3 + 2] = pz * invR;
    g_pc[i * 3 + 0] = px * invRc; g_pc[i * 3 + 1] = py * invRc; g_pc[i * 3 + 2] = pz * invRc;

    float nx = nrm[i * 3 + 0], ny = nrm[i * 3 + 1], nz = nrm[i * 3 + 2];
    float s = nz >= 0.f ? 1.f : -1.f;
    float a = -1.f / (s + nz);
    float b = nx * ny * a;
    g_uv[i * 6 + 0] = 1.f + s * nx * nx * a;
    g_uv[i * 6 + 1] = s * b;
    g_uv[i * 6 + 2] = -s * nx;
    g_uv[i * 6 + 3] = b;
    g_uv[i * 6 + 4] = s + ny * ny * a;
    g_uv[i * 6 + 5] = -ny;

    float h0[16];
#pragma unroll
    for (int u = 0; u < 16; u++) {
        float acc = sNib1[u];
#pragma unroll
        for (int k = 0; k < 16; k++) acc = fmaf(f[k], sNi1[u * 16 + k], acc);
        h0[u] = lk(acc);
    }
#pragma unroll
    for (int v = 0; v < 16; v++) {
        float acc = sNib2[v];
#pragma unroll
        for (int k = 0; k < 16; k++) acc = fmaf(h0[k], sNi2[v * 16 + k], acc);
        g_h1[i * 16 + v] = lk(acc);
    }
}

// ---------------- GroupNorm stats: 16 CTAs x 256 thr, one row each ----------------
__device__ void gns_body(const float* __restrict__ xin, float* __restrict__ part) {
    __shared__ float red[8][8];
    int t = threadIdx.x;
    int n = blockIdx.x * 256 + t;
    const float4* rp = reinterpret_cast<const float4*>(xin + n * 16);
    float4 v0 = rp[0], v1 = rp[1], v2 = rp[2], v3 = rp[3];
    float s0 = v0.x + v0.y + v0.z + v0.w, q0 = v0.x * v0.x + v0.y * v0.y + v0.z * v0.z + v0.w * v0.w;
    float s1 = v1.x + v1.y + v1.z + v1.w, q1 = v1.x * v1.x + v1.y * v1.y + v1.z * v1.z + v1.w * v1.w;
    float s2 = v2.x + v2.y + v2.z + v2.w, q2 = v2.x * v2.x + v2.y * v2.y + v2.z * v2.z + v2.w * v2.w;
    float s3 = v3.x + v3.y + v3.z + v3.w, q3 = v3.x * v3.x + v3.y * v3.y + v3.z * v3.z + v3.w * v3.w;
#pragma unroll
    for (int off = 16; off > 0; off >>= 1) {
        s0 += __shfl_down_sync(0xffffffffu, s0, off);
        s1 += __shfl_down_sync(0xffffffffu, s1, off);
        s2 += __shfl_down_sync(0xffffffffu, s2, off);
        s3 += __shfl_down_sync(0xffffffffu, s3, off);
        q0 += __shfl_down_sync(0xffffffffu, q0, off);
        q1 += __shfl_down_sync(0xffffffffu, q1, off);
        q2 += __shfl_down_sync(0xffffffffu, q2, off);
        q3 += __shfl_down_sync(0xffffffffu, q3, off);
    }
    int lane = t & 31, w = t >> 5;
    if (lane == 0) {
        red[w][0] = s0; red[w][1] = s1; red[w][2] = s2; red[w][3] = s3;
        red[w][4] = q0; red[w][5] = q1; red[w][6] = q2; red[w][7] = q3;
    }
    __syncthreads();
    if (t < 8) {
        float a = 0.f;
#pragma unroll
        for (int k = 0; k < 8; k++) a += red[k][t];
        part[blockIdx.x * 8 + t] = a;
    }
}
__global__ void kGNs1(int N) { gns_body(g_h1, g_part1); }
__global__ void kGNs2(int N) { gns_body(g_y2, g_part2); }

// stats finalize helper (in-block): fin[8] -> smean[4], sinv[4]
__device__ __forceinline__ void gn_finalize(const float* __restrict__ part,
                                            float* fin, float* smean, float* sinv, int N) {
    int t = threadIdx.x;
    if (t < 8) {
        float a = 0.f;
#pragma unroll
        for (int c = 0; c < 16; c++) a += part[c * 8 + t];
        fin[t] = a;
    }
    __syncthreads();
    if (t < 4) {
        float cnt = (float)(4 * N);
        float mn = fin[t] / cnt;
        float vv = fin[t + 4] / cnt - mn * mn;
        smean[t] = mn;
        sinv[t] = rsqrtf(vv + 1e-5f);
    }
    __syncthreads();
}

// ---------------- GroupNorm apply (gn_in): 256 CTAs ----------------
__global__ void kGNa_in(const float* __restrict__ gamma, const float* __restrict__ beta, int N) {
    __shared__ float fin[8], smean[4], sinv[4];
    gn_finalize(g_part1, fin, smean, sinv, N);
    int idx = blockIdx.x * 256 + threadIdx.x;
    int c = idx & 15;
    int gg = c >> 2;
    g_h[idx] = (g_h1[idx] - smean[gg]) * sinv[gg] * gamma[c] + beta[c];
}

// ---------------- GroupNorm apply (gn_out) fused with kE3 ----------------
__global__ void kGNaE3(const float* __restrict__ gamma, const float* __restrict__ beta,
                       const float* __restrict__ feats,
                       const float* __restrict__ llw1, const float* __restrict__ llb1,
                       const float* __restrict__ llw2, const float* __restrict__ llb2,
                       const float* __restrict__ ltw, const float* __restrict__ ltb,
                       float* __restrict__ out, int N) {
    __shared__ float fin[8], smean[4], sinv[4];
    __shared__ float yn_s[16][17], t1_s[16][17];
    __shared__ float sW1[256], sW2[256], sWt[256], sB1[16], sB2[16], sBt[16];
    int t = threadIdx.x;
    if (t < 256) { sW1[t] = llw1[t]; sW2[t] = llw2[t]; sWt[t] = ltw[t]; }
    if (t < 16)  { sB1[t] = llb1[t]; sB2[t] = llb2[t]; sBt[t] = ltb[t]; }
    gn_finalize(g_part2, fin, smean, sinv, N);

    int il = t >> 4, c = t & 15;
    int i = blockIdx.x * 16 + il;
    int gg = c >> 2;
    float x = g_y2[i * 16 + c];
    yn_s[il][c] = (x - smean[gg]) * sinv[gg] * gamma[c] + beta[c];
    __syncthreads();
    float a = sB1[c];
#pragma unroll
    for (int k = 0; k < 16; k++) a = fmaf(yn_s[il][k], sW1[c * 16 + k], a);
    t1_s[il][c] = fmaxf(a, 0.f);
    __syncthreads();
    float xi = sB2[c];
#pragma unroll
    for (int k = 0; k < 16; k++) xi = fmaf(t1_s[il][k], sW2[c * 16 + k], xi);
    float xl = sBt[c];
#pragma unroll
    for (int k = 0; k < 16; k++) xl = fmaf(feats[i * 16 + k], sWt[c * 16 + k], xl);
    out[i * 16 + c] = xl + xi;
}

// ---------------- Kernel C: load_mesh N^2 (coalesced j-interleave, 2-stream ILP) ----------------
// CTA = 4 i's x 64 j-lanes. Thread (il = t>>6, s = t&63) runs two independent
// j-streams: j = s + 128k and j = s + 64 + 128k (separate accumulators).
__global__ void kMesh(const float* __restrict__ nrm, int N) {
    __shared__ float sred[4][64][2];
    int t = threadIdx.x;
    int il = t >> 6, s = t & 63;
    int i = blockIdx.x * 4 + il;

    float pix = g_pm[i * 3 + 0], piy = g_pm[i * 3 + 1], piz = g_pm[i * 3 + 2];
    float nix = nrm[i * 3 + 0], niy = nrm[i * 3 + 1], niz = nrm[i * 3 + 2];
    float ux = g_uv[i * 6 + 0], uy = g_uv[i * 6 + 1], uz = g_uv[i * 6 + 2];
    float vx = g_uv[i * 6 + 3], vy = g_uv[i * 6 + 4], vz = g_uv[i * 6 + 5];

    float ov0a = 0.f, ov1a = 0.f, ov0b = 0.f, ov1b = 0.f;
#pragma unroll 2
    for (int j = s; j < N; j += 128) {
        int jb = j + 64;
        float dxa = g_pm[j * 3 + 0] - pix;
        float dya = g_pm[j * 3 + 1] - piy;
        float dza = g_pm[j * 3 + 2] - piz;
        float dxb = g_pm[jb * 3 + 0] - pix;
        float dyb = g_pm[jb * 3 + 1] - piy;
        float dzb = g_pm[jb * 3 + 2] - piz;
        float csa = nrm[j * 3 + 0] * nix + nrm[j * 3 + 1] * niy + nrm[j * 3 + 2] * niz;
        float csb = nrm[jb * 3 + 0] * nix + nrm[jb * 3 + 1] * niy + nrm[jb * 3 + 2] * niz;
        float d2a = dxa * dxa + dya * dya + dza * dza;
        float d2b = dxb * dxb + dyb * dyb + dzb * dzb;
        float tta = 2.f - csa;
        float ttb = 2.f - csb;
        float wja = __expf(-d2a * tta * tta) * g_scores[j];
        float wjb = __expf(-d2b * ttb * ttb) * g_scores[jb];
        ov0a = fmaf(wja, ux * dxa + uy * dya + uz * dza, ov0a);
        ov1a = fmaf(wja, vx * dxa + vy * dya + vz * dza, ov1a);
        ov0b = fmaf(wjb, ux * dxb + uy * dyb + uz * dzb, ov0b);
        ov1b = fmaf(wjb, vx * dxb + vy * dyb + vz * dzb, ov1b);
    }
    sred[il][s][0] = ov0a + ov0b;
    sred[il][s][1] = ov1a + ov1b;
    __syncthreads();
    if (t < 4) {
        float a0 = 0.f, a1 = 0.f;
#pragma unroll 8
        for (int k = 0; k < 64; k++) { a0 += sred[t][k][0]; a1 += sred[t][k][1]; }
        a0 += 1e-5f; a1 += 1e-5f;
        float nr = fmaxf(sqrtf(a0 * a0 + a1 * a1), 1e-12f);
        int ii = blockIdx.x * 4 + t;
        float ex = a0 / nr, ey = a1 / nr;
        float mx = nrm[ii * 3 + 0], my = nrm[ii * 3 + 1], mz = nrm[ii * 3 + 2];
        float uxx = g_uv[ii * 6 + 0], uyy = g_uv[ii * 6 + 1], uzz = g_uv[ii * 6 + 2];
        float vxx = g_uv[ii * 6 + 3], vyy = g_uv[ii * 6 + 4], vzz = g_uv[ii * 6 + 5];
        g_nuv[ii * 9 + 0] = mx; g_nuv[ii * 9 + 1] = my; g_nuv[ii * 9 + 2] = mz;
        g_nuv[ii * 9 + 3] = ex * uxx + ey * vxx;
        g_nuv[ii * 9 + 4] = ex * uyy + ey * vyy;
        g_nuv[ii * 9 + 5] = ex * uzz + ey * vzz;
        g_nuv[ii * 9 + 6] = -ey * uxx + ex * vxx;
        g_nuv[ii * 9 + 7] = -ey * uyy + ex * vyy;
        g_nuv[ii * 9 + 8] = -ey * uzz + ex * vzz;
    }
}

// ---------------- Kernel D: bf16 mma conv (R7 exact) + fused no_w MLP tail ----------------
__global__ void __launch_bounds__(256, 3)
kConvB(const float* __restrict__ nrm, const float* __restrict__ cva1,
       const float* __restrict__ cvb1, const float* __restrict__ cva2,
       const float* __restrict__ cvb2,
       const float* __restrict__ now1, const float* __restrict__ nob1,
       const float* __restrict__ now2, const float* __restrict__ nob2, int N) {
    __shared__ __align__(16) uint32_t sGp[128][12]; // words 0-3: hi pairs, 4-7: lo pairs
    __shared__ float sWh[128 * 17];
    __shared__ float sRed[8][4][4];
    __shared__ float s_a1[24], s_b1[8], s_pi[3], s_nv[9];
    __shared__ float yv[16], t1e[16];

    int t = threadIdx.x, lane = t & 31, w = t >> 5;
    int r = lane >> 2, q = lane & 3;
    int i = blockIdx.x;

    if (t < 24) s_a1[t] = cva1[t];
    else if (t < 32) s_b1[t - 24] = cvb1[t - 24];
    else if (t < 35) s_pi[t - 32] = g_pc[i * 3 + (t - 32)];
    else if (t < 44) s_nv[t - 35] = g_nuv[i * 9 + (t - 35)];

    uint32_t Bhi[4], Blo[4];
    float bias0[4], bias1[4];
#pragma unroll
    for (int lc = 0; lc < 4; lc++) {
        int h = 2 * w + (lc >> 1);
        int oB = (lc & 1) * 8 + r;
        const float* brow = cva2 + (oB * 16 + h) * 8;
        float v0 = brow[2 * q], v1 = brow[2 * q + 1];
        __nv_bfloat16 h0, l0, h1, l1;
        bfsplit(v0, h0, l0);
        bfsplit(v1, h1, l1);
        Bhi[lc] = pkbf(h0, h1);
        Blo[lc] = pkbf(l0, l1);
        int oC = (lc & 1) * 8 + 2 * q;
        bias0[lc] = cvb2[oC * 16 + h];
        bias1[lc] = cvb2[(oC + 1) * 16 + h];
    }
    __syncthreads();

    float y4[4] = {0.f, 0.f, 0.f, 0.f};

    for (int jt = 0; jt < N; jt += 128) {
        __syncthreads();
        {
            int jj = t & 127;
            int j = jt + jj;
            float pjx = g_pc[j * 3 + 0], pjy = g_pc[j * 3 + 1], pjz = g_pc[j * 3 + 2];
            float dx = pjx - s_pi[0], dy = pjy - s_pi[1], dz = pjz - s_pi[2];
            if (t < 128) {
                float X0 = dx * s_nv[0] + dy * s_nv[1] + dz * s_nv[2];
                float X1 = dx * s_nv[3] + dy * s_nv[4] + dz * s_nv[5];
                float X2 = dx * s_nv[6] + dy * s_nv[7] + dz * s_nv[8];
                uint32_t hp[4], lp[4];
#pragma unroll
                for (int c2 = 0; c2 < 4; c2++) {
                    float g0 = fmaf(X0, s_a1[(2 * c2) * 3 + 0],
                               fmaf(X1, s_a1[(2 * c2) * 3 + 1],
                               fmaf(X2, s_a1[(2 * c2) * 3 + 2], s_b1[2 * c2])));
                    float g1 = fmaf(X0, s_a1[(2 * c2 + 1) * 3 + 0],
                               fmaf(X1, s_a1[(2 * c2 + 1) * 3 + 1],
                               fmaf(X2, s_a1[(2 * c2 + 1) * 3 + 2], s_b1[2 * c2 + 1])));
                    g0 = fmaxf(g0, 0.f);
                    g1 = fmaxf(g1, 0.f);
                    __nv_bfloat16 h0, l0, h1, l1;
                    bfsplit(g0, h0, l0);
                    bfsplit(g1, h1, l1);
                    hp[c2] = pkbf(h0, h1);
                    lp[c2] = pkbf(l0, l1);
                }
                *reinterpret_cast<uint4*>(&sGp[jj][0]) = make_uint4(hp[0], hp[1], hp[2], hp[3]);
                *reinterpret_cast<uint4*>(&sGp[jj][4]) = make_uint4(lp[0], lp[1], lp[2], lp[3]);
            } else {
                float njx = nrm[j * 3 + 0], njy = nrm[j * 3 + 1], njz = nrm[j * 3 + 2];
                float d2 = dx * dx + dy * dy + dz * dz;
                float cs = njx * s_nv[0] + njy * s_nv[1] + njz * s_nv[2];
                float tt = 2.f - cs;
                float wv = __expf(-d2 * tt * tt);
                const float4* hp4 = reinterpret_cast<const float4*>(g_h + j * 16);
                float* whd = sWh + jj * 17;
#pragma unroll
                for (int c = 0; c < 4; c++) {
                    float4 h4 = hp4[c];
                    whd[4 * c + 0] = wv * h4.x;
                    whd[4 * c + 1] = wv * h4.y;
                    whd[4 * c + 2] = wv * h4.z;
                    whd[4 * c + 3] = wv * h4.w;
                }
            }
        }
        __syncthreads();

#pragma unroll 2
        for (int mt = 0; mt < 8; mt++) {
            int row0 = mt * 16 + r, row1 = row0 + 8;
            uint32_t a0 = sGp[row0][q];
            uint32_t a1 = sGp[row1][q];
            uint32_t a2 = sGp[row0][4 + q];
            uint32_t a3 = sGp[row1][4 + q];
            float whA0 = sWh[row0 * 17 + 2 * w];
            float whA1 = sWh[row1 * 17 + 2 * w];
            float whB0 = sWh[row0 * 17 + 2 * w + 1];
            float whB1 = sWh[row1 * 17 + 2 * w + 1];
#pragma unroll
            for (int lc = 0; lc < 4; lc++) {
                float c0 = bias0[lc], c1 = bias1[lc], c2 = bias0[lc], c3 = bias1[lc];
                mma16(c0, c1, c2, c3, a0, a1, a2, a3, Bhi[lc], Bhi[lc]);
                mma16(c0, c1, c2, c3, a0, a1, a2, a3, Blo[lc], Blo[lc]);
                float w0 = (lc >> 1) ? whB0 : whA0;
                float w1 = (lc >> 1) ? whB1 : whA1;
                int base = (lc & 1) * 2;
                y4[base + 0] = fmaf(reluf(c0), w0, fmaf(reluf(c2), w1, y4[base + 0]));
                y4[base + 1] = fmaf(reluf(c1), w0, fmaf(reluf(c3), w1, y4[base + 1]));
            }
        }
    }

#pragma unroll
    for (int off = 4; off < 32; off <<= 1) {
        y4[0] += __shfl_down_sync(0xffffffffu, y4[0], off);
        y4[1] += __shfl_down_sync(0xffffffffu, y4[1], off);
        y4[2] += __shfl_down_sync(0xffffffffu, y4[2], off);
        y4[3] += __shfl_down_sync(0xffffffffu, y4[3], off);
    }
    if (lane < 4) {
        sRed[w][lane][0] = y4[0];
        sRed[w][lane][1] = y4[1];
        sRed[w][lane][2] = y4[2];
        sRed[w][lane][3] = y4[3];
    }
    __syncthreads();
    if (t < 16) {
        int o = t;
        int qq = (o & 7) >> 1;
        int slot = (o & 1) + ((o >> 3) << 1);
        float a = 0.f;
#pragma unroll
        for (int ww = 0; ww < 8; ww++) a += sRed[ww][qq][slot];
        yv[o] = a;
    }
    __syncthreads();
    if (t < 16) {
        float a = nob1[t];
#pragma unroll
        for (int k = 0; k < 16; k++) a = fmaf(yv[k], now1[t * 16 + k], a);
        t1e[t] = lk(a);
    }
    __syncthreads();
    if (t < 16) {
        float a = nob2[t];
#pragma unroll
        for (int k = 0; k < 16; k++) a = fmaf(t1e[k], now2[t * 16 + k], a);
        g_y2[i * 16 + t] = lk(a);
    }
}

// ---------------- launch ----------------
extern "C" void kernel_launch(void* const* d_in, const int* in_sizes, int n_in,
                              void* d_out, int out_size) {
    const float* xyz    = (const float*)d_in[0];
    const float* nrm    = (const float*)d_in[1];
    const float* feats  = (const float*)d_in[2];
    const float* osw1   = (const float*)d_in[3];
    const float* osb1   = (const float*)d_in[4];
    const float* osw2   = (const float*)d_in[5];
    const float* osb2   = (const float*)d_in[6];
    const float* niw1   = (const float*)d_in[7];
    const float* nib1   = (const float*)d_in[8];
    const float* niw2   = (const float*)d_in[9];
    const float* nib2   = (const float*)d_in[10];
    const float* gnig   = (const float*)d_in[11];
    const float* gnib   = (const float*)d_in[12];
    const float* cva1   = (const float*)d_in[13];
    const float* cvb1   = (const float*)d_in[14];
    const float* cva2   = (const float*)d_in[15];
    const float* cvb2   = (const float*)d_in[16];
    const float* now1   = (const float*)d_in[17];
    const float* nob1   = (const float*)d_in[18];
    const float* now2   = (const float*)d_in[19];
    const float* nob2   = (const float*)d_in[20];
    const float* gnog   = (const float*)d_in[21];
    const float* gnob   = (const float*)d_in[22];
    const float* llw1   = (const float*)d_in[23];
    const float* llb1   = (const float*)d_in[24];
    const float* llw2   = (const float*)d_in[25];
    const float* llb2   = (const float*)d_in[26];
    const float* ltw    = (const float*)d_in[27];
    const float* ltb    = (const float*)d_in[28];
    float* out = (float*)d_out;

    int N = in_sizes[0] / 3;  // 4096

    kA<<<(N + 255) / 256, 256>>>(xyz, nrm, feats, osw1, osb1, osw2, osb2,
                                 niw1, nib1, niw2, nib2, N);
    kGNs1<<<N / 256, 256>>>(N);
    kGNa_in<<<N * 16 / 256, 256>>>(gnig, gnib, N);
    kMesh<<<N / 4, 256>>>(nrm, N);
    kConvB<<<N, 256>>>(nrm, cva1, cvb1, cva2, cvb2, now1, nob1, now2, nob2, N);
    kGNs2<<<N / 256, 256>>>(N);
    kGNaE3<<<N / 16, 256>>>(gnog, gnob, feats, llw1, llb1, llw2, llb2, ltw, ltb, out, N);
}